// round 6
// baseline (speedup 1.0000x reference)
#include <cuda_runtime.h>
#include <cstdint>

// Conv2d N=32, Cin=64, 64x64, Cout=128, 3x3 s1 p1, fp32.
// Implicit GEMM on mma.sync.m16n8k8.tf32.
// R6 = R4 shape (16 warps, warp tile 64x32, 125 regs) +
//   (a) paired (k,k+4) A layout -> a-frags via LDS.64 (8+4 LDS per tap,s)
//   (b) batched two-phase staging (MLP ~24) to kill long_scoreboard stalls.
//
// CTA: one n, 4 output rows -> M=256 (4y x 64x), N=128, K=576.

#define HW  64
#define CO  128
#define CIN 64

#define SB_ROW    264
#define SB_FLOATS (144 * SB_ROW)          // 38016
#define SA_OFF    SB_FLOATS
#define PS        808                     // pair stride (6*66*2=792 data), 8 mod 32
#define SMEM_BYTES ((SB_FLOATS + 16 * PS) * 4)   // 203,776 B

__device__ __forceinline__ uint32_t f2tf32(float f) {
    uint32_t r; asm("cvt.rna.tf32.f32 %0, %1;" : "=r"(r) : "f"(f)); return r;
}
__device__ __forceinline__ void mma8(float c[4], uint2 a0, uint2 a1, uint2 b) {
    // a0 = {A[m,k], A[m,k+4]}, a1 = {A[m+8,k], A[m+8,k+4]}
    asm volatile(
        "mma.sync.aligned.m16n8k8.row.col.f32.tf32.tf32.f32 "
        "{%0,%1,%2,%3}, {%4,%5,%6,%7}, {%8,%9}, {%0,%1,%2,%3};"
        : "+f"(c[0]), "+f"(c[1]), "+f"(c[2]), "+f"(c[3])
        : "r"(a0.x), "r"(a1.x), "r"(a0.y), "r"(a1.y), "r"(b.x), "r"(b.y));
}

__global__ void __launch_bounds__(512, 1)
conv_mma_kernel(const float* __restrict__ in, const float* __restrict__ w,
                const float* __restrict__ bias, float* __restrict__ out)
{
    extern __shared__ float sm[];

    const int tid   = threadIdx.x;
    const int lane  = tid & 31;
    const int warp  = tid >> 5;
    const int wy    = warp >> 2;        // 0..3 -> y row within tile
    const int warpN = warp & 3;         // 0..3 -> co 32-block
    const int y0    = blockIdx.x * 4;
    const int n     = blockIdx.y;

    const int r = lane >> 2;            // 0..7
    const int j = lane & 3;             // 0..3

    float acc[4][4][4];
#pragma unroll
    for (int mt = 0; mt < 4; ++mt)
#pragma unroll
        for (int nt = 0; nt < 4; ++nt)
#pragma unroll
            for (int q = 0; q < 4; ++q) acc[mt][nt][q] = 0.f;

    for (int chunk = 0; chunk < 2; ++chunk) {
        const int cib = chunk * 32;
        __syncthreads();   // previous chunk's LDS reads complete

        // ---- stage A (batched): 32ci x 6row x 66col -> (k,k+4)-paired smem ----
        const float* inb = in + ((size_t)n * CIN + cib) * (HW * HW);
        {
            float va[25];
#pragma unroll
            for (int it = 0; it < 25; ++it) {
                int e = it * 512 + tid;
                float v = 0.f;
                if (e < 32 * 396) {
                    int p   = e / 66;
                    int col = e - p * 66;
                    int ci  = p / 6;
                    int row = p - ci * 6;
                    int gy  = y0 - 1 + row;
                    int gx  = col - 1;
                    if ((unsigned)gy < (unsigned)HW && (unsigned)gx < (unsigned)HW)
                        v = inb[((size_t)ci * HW + gy) * HW + gx];
                }
                va[it] = v;
            }
#pragma unroll
            for (int it = 0; it < 25; ++it) {
                int e = it * 512 + tid;
                if (e < 32 * 396) {
                    int p    = e / 66;
                    int col  = e - p * 66;
                    int ci   = p / 6;
                    int row  = p - ci * 6;
                    int s    = ci >> 3;
                    int rem  = ci & 7;
                    int pair = s * 4 + (rem & 3);
                    int slot = rem >> 2;
                    sm[SA_OFF + pair * PS + (row * 66 + col) * 2 + slot] =
                        __uint_as_float(f2tf32(va[it]));
                }
            }
        }

        // ---- stage B (batched, 3 groups of 12): pairs (k, k+4) per co ----
        const float* wb = w + (size_t)cib * 9 * CO;
        for (int g = 0; g < 3; ++g) {
            float v0[12], v1[12];
#pragma unroll
            for (int i = 0; i < 12; ++i) {
                int e    = (g * 12 + i) * 512 + tid;      // < 18432 exactly
                int co   = e & 127;
                int rowp = e >> 7;
                int tap  = rowp >> 4;
                int s    = (rowp >> 2) & 3;
                int jj   = rowp & 3;
                int k    = s * 8 + jj;
                v0[i] = wb[((size_t)k * 9 + tap) * CO + co];
                v1[i] = wb[((size_t)(k + 4) * 9 + tap) * CO + co];
            }
#pragma unroll
            for (int i = 0; i < 12; ++i) {
                int e    = (g * 12 + i) * 512 + tid;
                int co   = e & 127;
                int rowp = e >> 7;
                float2 pv;
                pv.x = __uint_as_float(f2tf32(v0[i]));
                pv.y = __uint_as_float(f2tf32(v1[i]));
                *(float2*)&sm[rowp * SB_ROW + 2 * co] = pv;
            }
        }
        __syncthreads();

        // ---- compute: 9 taps x 4 ksteps, warp tile 64x32 ----
#pragma unroll
        for (int tap = 0; tap < 9; ++tap) {
            const int dy = tap / 3 - 1;
            const int dx = tap % 3 - 1;
            const float* pA = &sm[SA_OFF + j * PS
                                  + ((wy + dy + 1) * 66 + 1 + dx + r) * 2];
            const float* pB = &sm[(tap * 16 + j) * SB_ROW + 2 * (warpN * 32 + r)];
#pragma unroll
            for (int s = 0; s < 4; ++s) {
                const float* pAs = pA + s * 4 * PS;
                uint2 a[4][2];
#pragma unroll
                for (int mt = 0; mt < 4; ++mt) {
                    a[mt][0] = *(const uint2*)(pAs + mt * 32);       // m=mt*16+r
                    a[mt][1] = *(const uint2*)(pAs + mt * 32 + 16);  // m=mt*16+r+8
                }
                const float* pBs = pB + s * 4 * SB_ROW;
#pragma unroll
                for (int nt = 0; nt < 4; ++nt) {
                    uint2 b = *(const uint2*)&pBs[nt * 16];
#pragma unroll
                    for (int mt = 0; mt < 4; ++mt)
                        mma8(acc[mt][nt], a[mt][0], a[mt][1], b);
                }
            }
        }
    }

    // ---- epilogue: c frag rows (r, r+8), cols (2j, 2j+1) ----
    const int y = y0 + wy;
#pragma unroll
    for (int nt = 0; nt < 4; ++nt) {
        int co = warpN * 32 + nt * 8 + 2 * j;
        float b0 = __ldg(bias + co);
        float b1 = __ldg(bias + co + 1);
        float* o0 = out + (((size_t)n * CO + co) * HW + y) * HW;
#pragma unroll
        for (int mt = 0; mt < 4; ++mt) {
            int x = mt * 16 + r;
            o0[x]               = acc[mt][nt][0] + b0;
            o0[HW * HW + x]     = acc[mt][nt][1] + b1;
            o0[x + 8]           = acc[mt][nt][2] + b0;
            o0[HW * HW + x + 8] = acc[mt][nt][3] + b1;
        }
    }
}

extern "C" void kernel_launch(void* const* d_in, const int* in_sizes, int n_in,
                              void* d_out, int out_size)
{
    const float* in   = (const float*)d_in[0];
    const float* w    = (const float*)d_in[1];
    const float* bias = (const float*)d_in[2];
    float* out        = (float*)d_out;

    cudaFuncSetAttribute(conv_mma_kernel,
                         cudaFuncAttributeMaxDynamicSharedMemorySize, SMEM_BYTES);
    dim3 grid(16, 32);
    conv_mma_kernel<<<grid, 512, SMEM_BYTES>>>(in, w, bias, out);
}

// round 7
// speedup vs baseline: 1.0680x; 1.0680x over previous
#include <cuda_runtime.h>
#include <cstdint>

// Conv2d N=32, Cin=64, 64x64, Cout=128, 3x3 s1 p1, fp32.
// Implicit GEMM on mma.sync.m16n8k8.tf32.
// R7 = R4 (16 warps, warp tile 64x32, rolled staging, 125 regs) with ONE
// change: A stored as (k,k+4) pairs so a-frags load via LDS.64
// (8 LDS.64 instead of 16 LDS.32 per (tap,s)). Pair stride 808 = 8 mod 32
// keeps every LDS.64 phase bank-conflict-free.
//
// CTA: one n, 4 output rows -> M=256 (4y x 64x), N=128, K=576.

#define HW  64
#define CO  128
#define CIN 64

#define SB_ROW    264
#define SB_FLOATS (144 * SB_ROW)          // 38016
#define SA_OFF    SB_FLOATS
#define PS        808                     // pair stride (6*66*2=792 data), 8 mod 32
#define SMEM_BYTES ((SB_FLOATS + 16 * PS) * 4)   // 203,776 B

__device__ __forceinline__ uint32_t f2tf32(float f) {
    uint32_t r; asm("cvt.rna.tf32.f32 %0, %1;" : "=r"(r) : "f"(f)); return r;
}
__device__ __forceinline__ void mma8(float c[4], uint2 a0, uint2 a1, uint2 b) {
    // a0 = {A[m,k], A[m,k+4]}, a1 = {A[m+8,k], A[m+8,k+4]}
    asm volatile(
        "mma.sync.aligned.m16n8k8.row.col.f32.tf32.tf32.f32 "
        "{%0,%1,%2,%3}, {%4,%5,%6,%7}, {%8,%9}, {%0,%1,%2,%3};"
        : "+f"(c[0]), "+f"(c[1]), "+f"(c[2]), "+f"(c[3])
        : "r"(a0.x), "r"(a1.x), "r"(a0.y), "r"(a1.y), "r"(b.x), "r"(b.y));
}

__global__ void __launch_bounds__(512, 1)
conv_mma_kernel(const float* __restrict__ in, const float* __restrict__ w,
                const float* __restrict__ bias, float* __restrict__ out)
{
    extern __shared__ float sm[];

    const int tid   = threadIdx.x;
    const int lane  = tid & 31;
    const int warp  = tid >> 5;
    const int wy    = warp >> 2;        // 0..3 -> y row within tile
    const int warpN = warp & 3;         // 0..3 -> co 32-block
    const int y0    = blockIdx.x * 4;
    const int n     = blockIdx.y;

    const int r = lane >> 2;            // 0..7
    const int j = lane & 3;             // 0..3

    float acc[4][4][4];
#pragma unroll
    for (int mt = 0; mt < 4; ++mt)
#pragma unroll
        for (int nt = 0; nt < 4; ++nt)
#pragma unroll
            for (int q = 0; q < 4; ++q) acc[mt][nt][q] = 0.f;

    for (int chunk = 0; chunk < 2; ++chunk) {
        const int cib = chunk * 32;
        __syncthreads();   // previous chunk's LDS reads complete

        // ---- stage A (rolled, R4-style): 32ci x 6row x 66col -> paired ----
        const float* inb = in + ((size_t)n * CIN + cib) * (HW * HW);
        for (int e = tid; e < 32 * 396; e += 512) {
            int p   = e / 66;           // ci*6 + row
            int col = e - p * 66;
            int ci  = p / 6;
            int row = p - ci * 6;
            int gy  = y0 - 1 + row;
            int gx  = col - 1;
            float v = 0.f;
            if ((unsigned)gy < (unsigned)HW && (unsigned)gx < (unsigned)HW)
                v = inb[((size_t)ci * HW + gy) * HW + gx];
            int s    = ci >> 3;
            int rem  = ci & 7;
            int pair = s * 4 + (rem & 3);
            int slot = rem >> 2;
            sm[SA_OFF + pair * PS + (row * 66 + col) * 2 + slot] =
                __uint_as_float(f2tf32(v));
        }

        // ---- stage B (rolled, R4-style): rows (tap,s,j) pairs (k,k+4) ----
        const float* wb = w + (size_t)cib * 9 * CO;
        for (int e = tid; e < 144 * 128; e += 512) {
            int co   = e & 127;
            int rowp = e >> 7;              // 0..143
            int tap  = rowp >> 4;
            int s    = (rowp >> 2) & 3;
            int jj   = rowp & 3;
            int k    = s * 8 + jj;
            float2 pv;
            pv.x = __uint_as_float(f2tf32(wb[((size_t)k * 9 + tap) * CO + co]));
            pv.y = __uint_as_float(f2tf32(wb[((size_t)(k + 4) * 9 + tap) * CO + co]));
            *(float2*)&sm[rowp * SB_ROW + 2 * co] = pv;
        }
        __syncthreads();

        // ---- compute: 9 taps x 4 ksteps, warp tile 64x32 ----
#pragma unroll
        for (int tap = 0; tap < 9; ++tap) {
            const int dy = tap / 3 - 1;
            const int dx = tap % 3 - 1;
            const float* pA = &sm[SA_OFF + j * PS
                                  + ((wy + dy + 1) * 66 + 1 + dx + r) * 2];
            const float* pB = &sm[(tap * 16 + j) * SB_ROW + 2 * (warpN * 32 + r)];
#pragma unroll
            for (int s = 0; s < 4; ++s) {
                const float* pAs = pA + s * 4 * PS;
                uint2 a[4][2];
#pragma unroll
                for (int mt = 0; mt < 4; ++mt) {
                    a[mt][0] = *(const uint2*)(pAs + mt * 32);       // m=mt*16+r
                    a[mt][1] = *(const uint2*)(pAs + mt * 32 + 16);  // m=mt*16+r+8
                }
                const float* pBs = pB + s * 4 * SB_ROW;
#pragma unroll
                for (int nt = 0; nt < 4; ++nt) {
                    uint2 b = *(const uint2*)&pBs[nt * 16];
#pragma unroll
                    for (int mt = 0; mt < 4; ++mt)
                        mma8(acc[mt][nt], a[mt][0], a[mt][1], b);
                }
            }
        }
    }

    // ---- epilogue: c frag rows (r, r+8), cols (2j, 2j+1) ----
    const int y = y0 + wy;
#pragma unroll
    for (int nt = 0; nt < 4; ++nt) {
        int co = warpN * 32 + nt * 8 + 2 * j;
        float b0 = __ldg(bias + co);
        float b1 = __ldg(bias + co + 1);
        float* o0 = out + (((size_t)n * CO + co) * HW + y) * HW;
#pragma unroll
        for (int mt = 0; mt < 4; ++mt) {
            int x = mt * 16 + r;
            o0[x]               = acc[mt][nt][0] + b0;
            o0[HW * HW + x]     = acc[mt][nt][1] + b1;
            o0[x + 8]           = acc[mt][nt][2] + b0;
            o0[HW * HW + x + 8] = acc[mt][nt][3] + b1;
        }
    }
}

extern "C" void kernel_launch(void* const* d_in, const int* in_sizes, int n_in,
                              void* d_out, int out_size)
{
    const float* in   = (const float*)d_in[0];
    const float* w    = (const float*)d_in[1];
    const float* bias = (const float*)d_in[2];
    float* out        = (float*)d_out;

    cudaFuncSetAttribute(conv_mma_kernel,
                         cudaFuncAttributeMaxDynamicSharedMemorySize, SMEM_BYTES);
    dim3 grid(16, 32);
    conv_mma_kernel<<<grid, 512, SMEM_BYTES>>>(in, w, bias, out);
}

// round 8
// speedup vs baseline: 1.3987x; 1.3097x over previous
#include <cuda_runtime.h>
#include <cstdint>

// Conv2d N=32, Cin=64, 64x64, Cout=128, 3x3 s1 p1, fp32.
// Implicit GEMM on mma.sync.m16n8k8.tf32.
// R8 = R4's compute loop VERBATIM (scalar LDS a-frags; any deviation raised
// ALU 2-3x in R5/R6/R7) + asynchronous staging:
//   - prep_b pre-kernel builds the per-chunk B smem image in global memory
//     (tf32-rounded, (k,k+4)-paired, SB_ROW-padded) -> B staging is pure
//     16B cp.async copies.
//   - A staged with 4B cp.async (zfill for halo OOB), then an in-place
//     smem tf32 convert sweep.

#define HW  64
#define CO  128
#define CIN 64

#define SB_ROW    264
#define SB_FLOATS (144 * SB_ROW)          // 38016
#define SA_OFF    SB_FLOATS
#define SA_CI     424                     // 6*66=396 data + pad; 8 mod 32
#define SA_WORDS  (32 * SA_CI)            // 13568
#define SMEM_BYTES ((SB_FLOATS + SA_WORDS) * 4)   // 206,336 B

__device__ __align__(16) float g_bimg[2 * 144 * SB_ROW];

__device__ __forceinline__ uint32_t f2tf32(float f) {
    uint32_t r; asm("cvt.rna.tf32.f32 %0, %1;" : "=r"(r) : "f"(f)); return r;
}
__device__ __forceinline__ void mma8(float c[4], const uint32_t a[4], uint2 b) {
    asm volatile(
        "mma.sync.aligned.m16n8k8.row.col.f32.tf32.tf32.f32 "
        "{%0,%1,%2,%3}, {%4,%5,%6,%7}, {%8,%9}, {%0,%1,%2,%3};"
        : "+f"(c[0]), "+f"(c[1]), "+f"(c[2]), "+f"(c[3])
        : "r"(a[0]), "r"(a[1]), "r"(a[2]), "r"(a[3]), "r"(b.x), "r"(b.y));
}
__device__ __forceinline__ uint32_t smem_u32(const void* p) {
    uint32_t a;
    asm("{ .reg .u64 t; cvta.to.shared.u64 t, %1; cvt.u32.u64 %0, t; }"
        : "=r"(a) : "l"(p));
    return a;
}

// Build B image: g_bimg[chunk][rowp=tap*16+s*4+j][2*co + slot] with
// slot0 = w[k], slot1 = w[k+4], k = s*8+j, ci = chunk*32 + k, tf32-rounded.
__global__ void __launch_bounds__(256)
prep_b(const float* __restrict__ w)
{
    int e  = blockIdx.x * 256 + threadIdx.x;    // 0..36863
    int co = e & 127;
    int rp = e >> 7;                            // chunk*144 + rowp
    int chunk = rp / 144;
    int rowp  = rp - chunk * 144;
    int tap = rowp >> 4;
    int s   = (rowp >> 2) & 3;
    int jj  = rowp & 3;
    int k   = s * 8 + jj;
    const float* wb = w + (size_t)(chunk * 32) * 9 * CO;
    float2 pv;
    pv.x = __uint_as_float(f2tf32(wb[((size_t)k * 9 + tap) * CO + co]));
    pv.y = __uint_as_float(f2tf32(wb[((size_t)(k + 4) * 9 + tap) * CO + co]));
    *(float2*)&g_bimg[(size_t)rp * SB_ROW + 2 * co] = pv;
}

__global__ void __launch_bounds__(512, 1)
conv_mma_kernel(const float* __restrict__ in, const float* __restrict__ bias,
                float* __restrict__ out)
{
    extern __shared__ float sm[];
    const uint32_t sbase = smem_u32(sm);

    const int tid   = threadIdx.x;
    const int lane  = tid & 31;
    const int warp  = tid >> 5;
    const int wy    = warp >> 2;        // 0..3 -> y row within tile
    const int warpN = warp & 3;         // 0..3 -> co 32-block
    const int y0    = blockIdx.x * 4;
    const int n     = blockIdx.y;

    const int r = lane >> 2;            // 0..7
    const int j = lane & 3;             // 0..3

    float acc[4][4][4];
#pragma unroll
    for (int mt = 0; mt < 4; ++mt)
#pragma unroll
        for (int nt = 0; nt < 4; ++nt)
#pragma unroll
            for (int q = 0; q < 4; ++q) acc[mt][nt][q] = 0.f;

    for (int chunk = 0; chunk < 2; ++chunk) {
        const int cib = chunk * 32;
        __syncthreads();   // previous chunk's LDS reads complete

        // ---- stage A via cp.async (4B, zfill OOB), raw fp32 ----
        const float* inb = in + ((size_t)n * CIN + cib) * (HW * HW);
        for (int e = tid; e < 32 * 396; e += 512) {
            int p   = e / 66;           // ci*6 + row
            int col = e - p * 66;
            int ci  = p / 6;
            int row = p - ci * 6;
            int gy  = y0 - 1 + row;
            int gx  = col - 1;
            bool ok = ((unsigned)gy < (unsigned)HW) && ((unsigned)gx < (unsigned)HW);
            const float* src = inb + ((size_t)ci * HW + (ok ? gy : 0)) * HW
                                   + (ok ? gx : 0);
            uint32_t dst = sbase + (uint32_t)(SA_OFF + ci * SA_CI + row * 66 + col) * 4u;
            uint32_t sz  = ok ? 4u : 0u;
            asm volatile("cp.async.ca.shared.global [%0], [%1], 4, %2;"
                         :: "r"(dst), "l"(src), "r"(sz) : "memory");
        }

        // ---- stage B via cp.async (16B) from prebuilt image ----
        const float* bimg = g_bimg + (size_t)chunk * 144 * SB_ROW;
        for (int e = tid; e < 144 * 66; e += 512) {
            int rowp = e / 66;
            int g    = e - rowp * 66;
            uint32_t dst = sbase + (uint32_t)(rowp * SB_ROW) * 4u + (uint32_t)g * 16u;
            const float* src = bimg + (size_t)rowp * SB_ROW + g * 4;
            asm volatile("cp.async.cg.shared.global [%0], [%1], 16;"
                         :: "r"(dst), "l"(src) : "memory");
        }
        asm volatile("cp.async.commit_group;" ::: "memory");
        asm volatile("cp.async.wait_group 0;" ::: "memory");
        __syncthreads();

        // ---- in-place tf32 convert of A region ----
        for (int e = tid; e < SA_WORDS; e += 512) {
            uint32_t ad = sbase + (uint32_t)(SA_OFF + e) * 4u;
            float v;
            asm volatile("ld.shared.f32 %0, [%1];" : "=f"(v) : "r"(ad));
            uint32_t t = f2tf32(v);
            asm volatile("st.shared.b32 [%0], %1;" :: "r"(ad), "r"(t) : "memory");
        }
        __syncthreads();

        // ---- compute: 9 taps x 4 ksteps, warp tile 64x32 (R4 verbatim) ----
#pragma unroll
        for (int tap = 0; tap < 9; ++tap) {
            const int dy = tap / 3 - 1;
            const int dx = tap % 3 - 1;
            const float* pA = &sm[SA_OFF + j * SA_CI
                                  + (wy + dy + 1) * 66 + 1 + dx + r];
            const float* pB = &sm[(tap * 16 + j) * SB_ROW + 2 * (warpN * 32 + r)];
#pragma unroll
            for (int s = 0; s < 4; ++s) {
                const float* pAs = pA + s * 8 * SA_CI;
                uint32_t a[4][4];
#pragma unroll
                for (int mt = 0; mt < 4; ++mt) {
                    a[mt][0] = __float_as_uint(pAs[mt * 16]);
                    a[mt][1] = __float_as_uint(pAs[mt * 16 + 8]);
                    a[mt][2] = __float_as_uint(pAs[mt * 16 + 4 * SA_CI]);
                    a[mt][3] = __float_as_uint(pAs[mt * 16 + 8 + 4 * SA_CI]);
                }
                const float* pBs = pB + s * 4 * SB_ROW;
#pragma unroll
                for (int nt = 0; nt < 4; ++nt) {
                    uint2 b = *(const uint2*)&pBs[nt * 16];
#pragma unroll
                    for (int mt = 0; mt < 4; ++mt)
                        mma8(acc[mt][nt], a[mt], b);
                }
            }
        }
    }

    // ---- epilogue: c frag rows (r, r+8), cols (2j, 2j+1) ----
    const int y = y0 + wy;
#pragma unroll
    for (int nt = 0; nt < 4; ++nt) {
        int co = warpN * 32 + nt * 8 + 2 * j;
        float b0 = __ldg(bias + co);
        float b1 = __ldg(bias + co + 1);
        float* o0 = out + (((size_t)n * CO + co) * HW + y) * HW;
#pragma unroll
        for (int mt = 0; mt < 4; ++mt) {
            int x = mt * 16 + r;
            o0[x]               = acc[mt][nt][0] + b0;
            o0[HW * HW + x]     = acc[mt][nt][1] + b1;
            o0[x + 8]           = acc[mt][nt][2] + b0;
            o0[HW * HW + x + 8] = acc[mt][nt][3] + b1;
        }
    }
}

extern "C" void kernel_launch(void* const* d_in, const int* in_sizes, int n_in,
                              void* d_out, int out_size)
{
    const float* in   = (const float*)d_in[0];
    const float* w    = (const float*)d_in[1];
    const float* bias = (const float*)d_in[2];
    float* out        = (float*)d_out;

    prep_b<<<144, 256>>>(w);

    cudaFuncSetAttribute(conv_mma_kernel,
                         cudaFuncAttributeMaxDynamicSharedMemorySize, SMEM_BYTES);
    dim3 grid(16, 32);
    conv_mma_kernel<<<grid, 512, SMEM_BYTES>>>(in, bias, out);
}